// round 2
// baseline (speedup 1.0000x reference)
#include <cuda_runtime.h>

#define F_IN   10000
#define NROWS  4096
#define CT     500      // columns per tile
#define NCT    20       // column tiles (20*500 = 10000)
#define CK     32       // column chunk staged in smem
#define RT     256      // rows per block == threads per block
#define L2E    1.4426950408889634f
#define LN2    0.6931471805599453f

// scratch (no allocations allowed)
__device__ float g_pp[F_IN * 9];          // per-column packed params [col][m*3 + {mean,k,c2}]
__device__ float g_part[NCT * NROWS];     // per-(coltile,row) partial sums

__device__ __forceinline__ float ex2(float x) {
    float r; asm("ex2.approx.ftz.f32 %0, %1;" : "=f"(r) : "f"(x)); return r;
}
__device__ __forceinline__ float lg2(float x) {
    float r; asm("lg2.approx.ftz.f32 %0, %1;" : "=f"(r) : "f"(x)); return r;
}

// Kernel 1: fold w1 log-softmax, log(std), 1/(2 std^2), and the feature
// permutation into per-COLUMN constants, all scaled to base-2 domain.
__global__ void prep_kernel(const float* __restrict__ means,
                            const float* __restrict__ stds,
                            const float* __restrict__ w1,
                            const int*   __restrict__ idx) {
    int f = blockIdx.x * blockDim.x + threadIdx.x;
    if (f >= F_IN) return;
    float w0 = w1[f*3+0], wa = w1[f*3+1], wb = w1[f*3+2];
    float mw = fmaxf(w0, fmaxf(wa, wb));
    float lse = mw + logf(expf(w0-mw) + expf(wa-mw) + expf(wb-mw));
    int col = idx[f];
    #pragma unroll
    for (int m = 0; m < 3; m++) {
        float wm   = w1[f*3+m];
        float mean = means[f*3+m];
        float sd   = stds[f*3+m];
        // natural: t = (wm-lse) - log(sd) - 0.5*log(2pi) - 0.5*((x-mean)/sd)^2
        // base-2:  t2 = c2 - k*(x-mean)^2
        float c2 = (wm - lse - logf(sd) - 0.91893853320467274f) * L2E;
        float k  = 0.5f * L2E / (sd * sd);
        g_pp[col*9 + m*3 + 0] = mean;
        g_pp[col*9 + m*3 + 1] = k;
        g_pp[col*9 + m*3 + 2] = c2;
    }
}

// Kernel 2: main sweep. Block = (col tile bx, row tile by). Each thread owns
// one row; columns are staged through a padded SMEM tile so every warp
// processes ONE column per step (params = broadcast LDS) while global x reads
// stay fully coalesced.
__global__ __launch_bounds__(RT) void spn_main(const float* __restrict__ x) {
    __shared__ float xs[CK * (RT + 1)];   // [j][row], padded stride -> conflict-free
    __shared__ float ps[CK * 9];
    const int tid = threadIdx.x;
    const int c0  = blockIdx.x * CT;
    const int r0  = blockIdx.y * RT;

    float acc = 0.0f;   // base-2 log accumulator

    for (int cc = 0; cc < CT; cc += CK) {
        const int cw = min(CK, CT - cc);
        __syncthreads();   // previous chunk fully consumed
        // BUGFIX R1: cw*9 (=288) > RT (=256) -> must stride, not mask
        for (int e = tid; e < cw * 9; e += RT)
            ps[e] = g_pp[(size_t)(c0 + cc) * 9 + e];
        for (int e = tid; e < RT * cw; e += RT) {
            int j = e % cw;            // == lane for cw==32 -> coalesced LDG
            int i = e / cw;
            xs[j * (RT + 1) + i] = x[(size_t)(r0 + i) * F_IN + (c0 + cc + j)];
        }
        __syncthreads();

        #pragma unroll 4
        for (int j = 0; j < cw; j++) {
            float xv  = xs[j * (RT + 1) + tid];
            float m0  = ps[j*9+0], k0 = ps[j*9+1], a0 = ps[j*9+2];
            float m1  = ps[j*9+3], k1 = ps[j*9+4], a1 = ps[j*9+5];
            float m2p = ps[j*9+6], k2 = ps[j*9+7], a2 = ps[j*9+8];
            float d0 = xv - m0, d1 = xv - m1, d2 = xv - m2p;
            float t0 = fmaf(-k0 * d0, d0, a0);
            float t1 = fmaf(-k1 * d1, d1, a1);
            float t2 = fmaf(-k2 * d2, d2, a2);
            // logsumexp over 3 with only 2 exps: max term's exp == 1
            float hi  = fmaxf(t0, t1), lo = fminf(t0, t1);
            float mx  = fmaxf(hi, t2), md = fminf(hi, t2);
            float s   = ex2(md - mx) + ex2(lo - mx);
            acc += mx + lg2(1.0f + s);
        }
    }
    g_part[(size_t)blockIdx.x * NROWS + r0 + tid] = acc * LN2;
}

// Kernel 3: fold the 20 column-tile partials per row (deterministic order).
__global__ void reduce_kernel(float* __restrict__ out) {
    int n = blockIdx.x * blockDim.x + threadIdx.x;
    if (n >= NROWS) return;
    float s = 0.0f;
    #pragma unroll
    for (int t = 0; t < NCT; t++) s += g_part[t * NROWS + n];
    out[n] = s;
}

extern "C" void kernel_launch(void* const* d_in, const int* in_sizes, int n_in,
                              void* d_out, int out_size) {
    const float* x     = (const float*)d_in[0];
    const float* means = (const float*)d_in[1];
    const float* stds  = (const float*)d_in[2];
    const float* w1    = (const float*)d_in[3];
    // d_in[4..7] = w2..w5: provably no-ops (log_softmax over size-1 axis == 0)
    const int*   idx   = (const int*)d_in[8];

    prep_kernel<<<(F_IN + 255) / 256, 256>>>(means, stds, w1, idx);
    spn_main<<<dim3(NCT, NROWS / RT), RT>>>(x);
    reduce_kernel<<<(NROWS + 255) / 256, 256>>>((float*)d_out);
}

// round 3
// speedup vs baseline: 2.6194x; 2.6194x over previous
#include <cuda_runtime.h>

#define F_IN   10000
#define F_PAD  10240     // padded to 80 groups of 128 columns
#define NROWS  4096
#define GROUPS 80        // column groups of 128
#define C      4         // 32-col chunks per lane (4*32 = 128 cols per warp)
#define WARPS  4         // warps per block
#define RB     128       // rows per block
#define L2E    1.4426950408889634f
#define LN2    0.6931471805599453f

// scratch (no allocations allowed)
__device__ float g_pp[F_PAD * 9];           // per-column packed params [col][m*3 + {mean,k,c2}]
__device__ float g_part[GROUPS * NROWS];    // per-(group,row) partial sums (base-2)

__device__ __forceinline__ float ex2(float x) {
    float r; asm("ex2.approx.ftz.f32 %0, %1;" : "=f"(r) : "f"(x)); return r;
}
__device__ __forceinline__ float lg2(float x) {
    float r; asm("lg2.approx.ftz.f32 %0, %1;" : "=f"(r) : "f"(x)); return r;
}

// Kernel 1: fold w1 log-softmax, log(std), 1/(2 std^2), and the feature
// permutation into per-COLUMN base-2 constants. Padding columns [10000,10240)
// get params that make their contribution exactly 0:
//   t0 = 0 (k=0,c2=0), t1 = t2 = -1e30  ->  mx=0, s=0, term = 0 + lg2(1) = 0.
__global__ void prep_kernel(const float* __restrict__ means,
                            const float* __restrict__ stds,
                            const float* __restrict__ w1,
                            const int*   __restrict__ idx) {
    int f = blockIdx.x * blockDim.x + threadIdx.x;
    if (f >= F_PAD) return;
    if (f >= F_IN) {            // padding column (identity contribution)
        int col = f;
        g_pp[col*9 + 0] = 0.0f; g_pp[col*9 + 1] = 0.0f; g_pp[col*9 + 2] = 0.0f;
        g_pp[col*9 + 3] = 0.0f; g_pp[col*9 + 4] = 0.0f; g_pp[col*9 + 5] = -1e30f;
        g_pp[col*9 + 6] = 0.0f; g_pp[col*9 + 7] = 0.0f; g_pp[col*9 + 8] = -1e30f;
        return;
    }
    float w0 = w1[f*3+0], wa = w1[f*3+1], wb = w1[f*3+2];
    float mw = fmaxf(w0, fmaxf(wa, wb));
    float lse = mw + logf(expf(w0-mw) + expf(wa-mw) + expf(wb-mw));
    int col = idx[f];
    #pragma unroll
    for (int m = 0; m < 3; m++) {
        float wm   = w1[f*3+m];
        float mean = means[f*3+m];
        float sd   = stds[f*3+m];
        // natural: t = (wm-lse) - log(sd) - 0.5*log(2pi) - 0.5*((x-mean)/sd)^2
        // base-2:  t2 = c2 - k*(x-mean)^2
        float c2 = (wm - lse - logf(sd) - 0.91893853320467274f) * L2E;
        float k  = 0.5f * L2E / (sd * sd);
        g_pp[col*9 + m*3 + 0] = mean;
        g_pp[col*9 + m*3 + 1] = k;
        g_pp[col*9 + m*3 + 2] = c2;
    }
}

// Kernel 2: main sweep. Warp owns 128 columns (lane = column within each of 4
// 32-col chunks), params live in registers for the whole 128-row sweep.
// x reads are coalesced 128B LDGs straight from GMEM (each element read once
// globally -> streaming hint). Per row: 4 chunks summed per-lane, one 5-step
// butterfly, lane 0 stores the row partial. No smem, no barriers.
__global__ __launch_bounds__(WARPS * 32) void spn_main(const float* __restrict__ x) {
    const int lane = threadIdx.x & 31;
    const int w    = threadIdx.x >> 5;
    const int g    = blockIdx.x * WARPS + w;      // column group 0..79
    const int r0   = blockIdx.y * RB;
    const int cbase = g * 128 + lane;

    // Load per-lane params for 4 columns into registers (once).
    float pm[C][3], pk[C][3], pa[C][3];
    #pragma unroll
    for (int c = 0; c < C; c++) {
        const float* p = &g_pp[(size_t)(cbase + c * 32) * 9];
        #pragma unroll
        for (int m = 0; m < 3; m++) {
            pm[c][m] = __ldg(p + m*3 + 0);
            pk[c][m] = __ldg(p + m*3 + 1);
            pa[c][m] = __ldg(p + m*3 + 2);
        }
    }
    // OOB guard only matters for the last 2 groups (cols >= 10000).
    bool inb[C];
    #pragma unroll
    for (int c = 0; c < C; c++) inb[c] = (cbase + c * 32) < F_IN;

    const float* xbase = x + (size_t)r0 * F_IN + g * 128 + lane;

    #pragma unroll 2
    for (int r = 0; r < RB; r++) {
        const float* xr = xbase + (size_t)r * F_IN;
        float xv[C];
        #pragma unroll
        for (int c = 0; c < C; c++) xv[c] = inb[c] ? __ldcs(xr + c * 32) : 0.0f;

        float term = 0.0f;
        #pragma unroll
        for (int c = 0; c < C; c++) {
            float d0 = xv[c] - pm[c][0], d1 = xv[c] - pm[c][1], d2 = xv[c] - pm[c][2];
            float t0 = fmaf(-pk[c][0] * d0, d0, pa[c][0]);
            float t1 = fmaf(-pk[c][1] * d1, d1, pa[c][1]);
            float t2 = fmaf(-pk[c][2] * d2, d2, pa[c][2]);
            // logsumexp over 3 with only 2 exps: max term's exp == 1
            float hi = fmaxf(t0, t1), lo = fminf(t0, t1);
            float mx = fmaxf(hi, t2), md = fminf(hi, t2);
            float s  = ex2(md - mx) + ex2(lo - mx);
            term += mx + lg2(1.0f + s);
        }
        #pragma unroll
        for (int off = 16; off; off >>= 1)
            term += __shfl_xor_sync(0xffffffffu, term, off);
        if (lane == 0) g_part[(size_t)g * NROWS + r0 + r] = term;
    }
}

// Kernel 3: fold the 80 group partials per row (deterministic order), back to
// natural log at the end.
__global__ void reduce_kernel(float* __restrict__ out) {
    int n = blockIdx.x * blockDim.x + threadIdx.x;
    if (n >= NROWS) return;
    float s = 0.0f;
    #pragma unroll
    for (int t = 0; t < GROUPS; t++) s += g_part[(size_t)t * NROWS + n];
    out[n] = s * LN2;
}

extern "C" void kernel_launch(void* const* d_in, const int* in_sizes, int n_in,
                              void* d_out, int out_size) {
    const float* x     = (const float*)d_in[0];
    const float* means = (const float*)d_in[1];
    const float* stds  = (const float*)d_in[2];
    const float* w1    = (const float*)d_in[3];
    // d_in[4..7] = w2..w5: provably no-ops (log_softmax over size-1 axis == 0)
    const int*   idx   = (const int*)d_in[8];

    prep_kernel<<<(F_PAD + 255) / 256, 256>>>(means, stds, w1, idx);
    spn_main<<<dim3(GROUPS / WARPS, NROWS / RB), WARPS * 32>>>(x);
    reduce_kernel<<<(NROWS + 255) / 256, 256>>>((float*)d_out);
}

// round 5
// speedup vs baseline: 5.6815x; 2.1690x over previous
#include <cuda_runtime.h>

#define F_IN   10000
#define F_PAD  10240     // padded to 80 groups of 128 columns
#define NROWS  4096
#define GROUPS 80        // column groups of 128
#define C      4         // 32-col chunks per lane
#define WARPS  4         // warps per block (one group each)
#define RB     64        // rows per block
#define NPART  (GROUPS * 8)          // 640 partials per row
#define L2E    1.4426950408889634f
#define LN2    0.6931471805599453f
#define HL2PI2 1.3257480647361593f   // 0.5*log2(2*pi)

// scratch (no allocations allowed)
__device__ float g_pp[F_PAD * 9];            // per-column [m][{-K, B, C_}] base-2 Horner params
__device__ float g_part[(size_t)NROWS * NPART]; // per-row partials, row-major

__device__ __forceinline__ float ex2(float x) {
    float r; asm("ex2.approx.ftz.f32 %0, %1;" : "=f"(r) : "f"(x)); return r;
}
__device__ __forceinline__ float lg2(float x) {
    float r; asm("lg2.approx.ftz.f32 %0, %1;" : "=f"(r) : "f"(x)); return r;
}

// Kernel 1: fold w1 log-softmax, log(std), permutation into per-column base-2
// Horner constants: t_m(x) = (-K x + B) x + C_  ==  A - K (x-mean)^2.
// Pad columns contribute exactly 0: t0 = 0, t1 = t2 = -1e30.
__global__ void prep_kernel(const float* __restrict__ means,
                            const float* __restrict__ stds,
                            const float* __restrict__ w1,
                            const int*   __restrict__ idx) {
    int f = blockIdx.x * blockDim.x + threadIdx.x;
    if (f >= F_PAD) return;
    if (f >= F_IN) {
        float* q = &g_pp[(size_t)f * 9];
        q[0]=0.f; q[1]=0.f; q[2]=0.f;
        q[3]=0.f; q[4]=0.f; q[5]=-1e30f;
        q[6]=0.f; q[7]=0.f; q[8]=-1e30f;
        return;
    }
    float u0 = w1[f*3+0]*L2E, u1 = w1[f*3+1]*L2E, u2 = w1[f*3+2]*L2E;
    float mu = fmaxf(u0, fmaxf(u1, u2));
    float l2 = mu + lg2(ex2(u0-mu) + ex2(u1-mu) + ex2(u2-mu));  // log2 softmax denom
    int col = idx[f];
    float* q = &g_pp[(size_t)col * 9];
    float uu[3] = {u0, u1, u2};
    #pragma unroll
    for (int m = 0; m < 3; m++) {
        float mean = means[f*3+m];
        float sd   = stds[f*3+m];
        float K    = 0.7213475204444817f / (sd * sd);   // 0.5*log2(e)/sd^2
        float A    = (uu[m] - l2) - lg2(sd) - HL2PI2;
        q[m*3+0] = -K;
        q[m*3+1] = 2.0f * K * mean;
        q[m*3+2] = A - K * mean * mean;
    }
}

// Kernel 2: warp owns 128 columns (lane = column), params in registers for the
// whole row sweep, coalesced streaming LDG of x with 1-row software prefetch.
// Per row: per-lane (a = sum of mx, p = prod of (1+s)); 2-step butterfly
// (add a / multiply p), ONE lg2, lanes 0-7 store 8 partials.
__global__ __launch_bounds__(WARPS * 32) void spn_main(const float* __restrict__ x) {
    const int lane = threadIdx.x & 31;
    const int w    = threadIdx.x >> 5;
    const int g    = blockIdx.x * WARPS + w;      // column group 0..79
    const int r0   = blockIdx.y * RB;
    const int cbase = g * 128 + lane;

    float nk[C][3], pb[C][3], pc[C][3];
    #pragma unroll
    for (int c = 0; c < C; c++) {
        const float* p = &g_pp[(size_t)(cbase + c * 32) * 9];
        #pragma unroll
        for (int m = 0; m < 3; m++) {
            nk[c][m] = __ldg(p + m*3 + 0);
            pb[c][m] = __ldg(p + m*3 + 1);
            pc[c][m] = __ldg(p + m*3 + 2);
        }
    }
    bool inb[C];
    #pragma unroll
    for (int c = 0; c < C; c++) inb[c] = (cbase + c * 32) < F_IN;

    const float* xbase = x + (size_t)r0 * F_IN + g * 128 + lane;

    // Per-row body: compute, 2-step butterfly, single lg2, store 8 partials.
    auto body = [&](int rval, const float (&xval)[C]) {
        float a = 0.0f, p = 1.0f;
        #pragma unroll
        for (int c = 0; c < C; c++) {
            float xv = xval[c];
            float t0 = fmaf(fmaf(xv, nk[c][0], pb[c][0]), xv, pc[c][0]);
            float t1 = fmaf(fmaf(xv, nk[c][1], pb[c][1]), xv, pc[c][1]);
            float t2 = fmaf(fmaf(xv, nk[c][2], pb[c][2]), xv, pc[c][2]);
            float hi = fmaxf(t0, t1), lo = fminf(t0, t1);
            float mx = fmaxf(hi, t2), md = fminf(hi, t2);
            float s  = ex2(md - mx) + ex2(lo - mx);
            a += mx;
            p *= (1.0f + s);
        }
        a += __shfl_xor_sync(0xffffffffu, a, 16);
        p *= __shfl_xor_sync(0xffffffffu, p, 16);
        a += __shfl_xor_sync(0xffffffffu, a, 8);
        p *= __shfl_xor_sync(0xffffffffu, p, 8);
        float v = a + lg2(p);
        if (lane < 8)
            g_part[(size_t)(r0 + rval) * NPART + g * 8 + lane] = v;
    };

    float nxt[C];
    #pragma unroll
    for (int c = 0; c < C; c++) nxt[c] = inb[c] ? __ldcs(xbase + c * 32) : 0.0f;

    #pragma unroll 2
    for (int r = 0; r < RB - 1; r++) {
        float cur[C];
        #pragma unroll
        for (int c = 0; c < C; c++) cur[c] = nxt[c];
        const float* xq = xbase + (size_t)(r + 1) * F_IN;
        #pragma unroll
        for (int c = 0; c < C; c++) nxt[c] = inb[c] ? __ldcs(xq + c * 32) : 0.0f;
        body(r, cur);
    }
    body(RB - 1, nxt);
}

// Kernel 3: fold 640 partials per row (one warp per row, deterministic order).
__global__ void reduce_kernel(float* __restrict__ out) {
    const int lane = threadIdx.x & 31;
    const int n    = blockIdx.x * (blockDim.x >> 5) + (threadIdx.x >> 5);
    if (n >= NROWS) return;
    const float* p = &g_part[(size_t)n * NPART];
    float s = 0.0f;
    #pragma unroll
    for (int i = 0; i < NPART / 32; i++) s += p[lane + i * 32];
    #pragma unroll
    for (int off = 16; off; off >>= 1)
        s += __shfl_xor_sync(0xffffffffu, s, off);
    if (lane == 0) out[n] = s * LN2;
}

extern "C" void kernel_launch(void* const* d_in, const int* in_sizes, int n_in,
                              void* d_out, int out_size) {
    const float* x     = (const float*)d_in[0];
    const float* means = (const float*)d_in[1];
    const float* stds  = (const float*)d_in[2];
    const float* w1    = (const float*)d_in[3];
    // d_in[4..7] = w2..w5: provably no-ops (log_softmax over size-1 axis == 0)
    const int*   idx   = (const int*)d_in[8];

    prep_kernel<<<F_PAD / 128, 128>>>(means, stds, w1, idx);
    spn_main<<<dim3(GROUPS / WARPS, NROWS / RB), WARPS * 32>>>(x);
    reduce_kernel<<<NROWS / 8, 256>>>((float*)d_out);
}